// round 12
// baseline (speedup 1.0000x reference)
#include <cuda_runtime.h>
#include <cuda_fp16.h>
#include <cstdint>

#define D 64
#define MAXN 150208
#define KMAX 27
#define ASTRIDE 72

// ---- scratch (static device arrays: allocation-free) ----
__device__ __half g_out1h[(size_t)MAXN * D];  // conv1 output (fp16)
__device__ float g_sum[D];
__device__ float g_sq[D];
__device__ float g_bias[256];                 // sh @ W2
__device__ __half g_xh[(size_t)MAXN * D];     // x rounded to fp16
__device__ __half g_W1h[(size_t)KMAX * 4096]; // W1^T [k][n][c] fp16
__device__ __half g_W2h[256 * 64];            // (sc*W2)^T [n][c] fp16 (post-BN fold)
__device__ __half g_W3h[64 * 256];            // W3^T [n][c] fp16

// ============================================================
// helpers
// ============================================================
__device__ __forceinline__ uint32_t smem_u32(const void* p) {
    uint32_t a;
    asm("{ .reg .u64 t; cvta.to.shared.u64 t, %1; cvt.u32.u64 %0, t; }" : "=r"(a) : "l"(p));
    return a;
}

__device__ __forceinline__ void ldm_x4(uint32_t* r, uint32_t addr) {
    asm volatile("ldmatrix.sync.aligned.m8n8.x4.shared.b16 {%0,%1,%2,%3}, [%4];"
                 : "=r"(r[0]), "=r"(r[1]), "=r"(r[2]), "=r"(r[3]) : "r"(addr));
}

__device__ __forceinline__ void mma_f16(float* d, const uint32_t* a, const uint32_t* b) {
    asm volatile(
        "mma.sync.aligned.m16n8k16.row.col.f32.f16.f16.f32 "
        "{%0,%1,%2,%3},{%4,%5,%6,%7},{%8,%9},{%0,%1,%2,%3};"
        : "+f"(d[0]), "+f"(d[1]), "+f"(d[2]), "+f"(d[3])
        : "r"(a[0]), "r"(a[1]), "r"(a[2]), "r"(a[3]), "r"(b[0]), "r"(b[1]));
}

__device__ __forceinline__ void cpa16(uint32_t dst, const void* src, uint32_t sz) {
    asm volatile("cp.async.cg.shared.global [%0], [%1], 16, %2;"
                 :: "r"(dst), "l"(src), "r"(sz) : "memory");
}
#define CPA_COMMIT() asm volatile("cp.async.commit_group;" ::: "memory")
#define CPA_WAIT0()  asm volatile("cp.async.wait_group 0;" ::: "memory")
#define CPA_WAIT1()  asm volatile("cp.async.wait_group 1;" ::: "memory")

__device__ __forceinline__ uint32_t relu_h2(float a, float b) {
    __half2 h = __floats2half2_rn(fmaxf(a, 0.f), fmaxf(b, 0.f));
    return *(uint32_t*)&h;
}

// ============================================================
// prep (single kernel): x->fp16, W1^T fp16, W3^T fp16, zero stats
// ============================================================
__global__ void prep_kernel(const float* __restrict__ x,
                            const float* __restrict__ W1,
                            const float* __restrict__ W3,
                            int total8, int K) {
    const int tid = threadIdx.x;
    if (blockIdx.x == 0) {
        if (tid < D) { g_sum[tid] = 0.f; g_sq[tid] = 0.f; }
        for (int e = tid; e < 64 * 256; e += blockDim.x) {
            int n = e >> 8, c = e & 255;
            g_W3h[n * 256 + c] = __float2half_rn(W3[(size_t)c * 64 + n]);
        }
    }
    if (blockIdx.x < (unsigned)K) {
        const float* Wk = W1 + (size_t)blockIdx.x * 4096;
        __half* dh = g_W1h + (size_t)blockIdx.x * 4096;
        for (int e = tid; e < 4096; e += blockDim.x) {
            int n = e >> 6, c = e & 63;
            dh[n * 64 + c] = __float2half_rn(Wk[c * 64 + n]);
        }
    }
    int e = blockIdx.x * blockDim.x + tid;
    if (e >= total8) return;
    const float4* s = (const float4*)x + 2 * e;
    float4 a = s[0], b = s[1];
    uint4 o;
    __half2 h;
    h = __floats2half2_rn(a.x, a.y); o.x = *(uint32_t*)&h;
    h = __floats2half2_rn(a.z, a.w); o.y = *(uint32_t*)&h;
    h = __floats2half2_rn(b.x, b.y); o.z = *(uint32_t*)&h;
    h = __floats2half2_rn(b.z, b.w); o.w = *(uint32_t*)&h;
    ((uint4*)g_xh)[e] = o;
}

// ============================================================
// conv1 via mma.sync fp16: 256x64 tile per CTA, 4 warps,
// warp tile 64x64. Double-buffered cp.async pipeline.
// Chunk-parallel gather: 8-lane groups own a row -> coalesced lines.
// ============================================================
#define STAGE_HALVES ((256 + 64) * ASTRIDE)   // A + W, halves per stage
__global__ __launch_bounds__(128, 2) void conv1_mma_kernel(
    const int*   __restrict__ nbr_idx,
    const int*   __restrict__ nbr_mask,
    int N, int K)
{
    extern __shared__ __align__(16) __half sm[];
    __shared__ float s_sum[D], s_sq[D];

    const int tid  = threadIdx.x;         // 0..127
    const int wid  = tid >> 5;            // 0..3
    const int lane = tid & 31;
    const int row0 = blockIdx.x * 256;

    if (tid < D) { s_sum[tid] = 0.f; s_sq[tid] = 0.f; }

    const uint32_t uBase = smem_u32(sm);
    const uint32_t stageB = STAGE_HALVES * 2;   // bytes per stage

    uint32_t wSm[4];
#pragma unroll
    for (int j = 0; j < 4; ++j) {
        int f = tid + 128 * j;
        wSm[j] = uBase + (uint32_t)(256 * ASTRIDE + (f >> 3) * ASTRIDE) * 2 + (f & 7) * 16;
    }

    const int m0 = wid * 64;
    uint32_t aA[4];
#pragma unroll
    for (int mt = 0; mt < 4; ++mt)
        aA[mt] = uBase + (uint32_t)(((m0 + mt * 16 + (lane & 15)) * ASTRIDE
                                     + (lane >> 4) * 8) * 2);
    uint32_t aB[4];
#pragma unroll
    for (int nb = 0; nb < 4; ++nb)
        aB[nb] = uBase + (uint32_t)((256 * ASTRIDE
                  + (nb * 16 + (lane & 7) + ((lane >> 4) << 3)) * ASTRIDE
                  + ((lane >> 3) & 1) * 8) * 2);

    float acc[4][8][4];
#pragma unroll
    for (int mt = 0; mt < 4; ++mt)
#pragma unroll
        for (int nt = 0; nt < 8; ++nt)
#pragma unroll
            for (int e = 0; e < 4; ++e) acc[mt][nt][e] = 0.f;

    const int grp = lane >> 3;   // row-in-quad 0..3
    const int ch  = lane & 7;    // 16B chunk 0..7

    auto issue = [&](int k, int s) {
        const uint32_t so = (uint32_t)s * stageB;
        // W tile (8KB)
        const char* wb = (const char*)(g_W1h + (size_t)k * 4096);
#pragma unroll
        for (int j = 0; j < 4; ++j)
            cpa16(wSm[j] + so, wb + (size_t)((tid + 128 * j) * 16), 16);
        // chunk-parallel masked gather: per instr, 4 whole 128B rows
        const size_t kN = (size_t)k * N;
#pragma unroll
        for (int i = 0; i < 16; ++i) {
            int lrow = (wid << 6) + (i << 2) + grp;
            int grow = row0 + lrow;
            int m = 0, idx = 0;
            if (grow < N) {
                m = nbr_mask[kN + grow];
                if (m) idx = nbr_idx[kN + grow];
            }
            const char* src = (const char*)(g_xh + (size_t)idx * D) + ch * 16;
            uint32_t dst = uBase + so + (uint32_t)(lrow * ASTRIDE) * 2 + ch * 16;
            cpa16(dst, src, m ? 16u : 0u);
        }
        CPA_COMMIT();
    };

    issue(0, 0);

    for (int k = 0; k < K; ++k) {
        const int s = k & 1;
        if (k + 1 < K) { issue(k + 1, s ^ 1); CPA_WAIT1(); }
        else           { CPA_WAIT0(); }
        __syncthreads();

        const uint32_t so = (uint32_t)s * stageB;
#pragma unroll
        for (int kk = 0; kk < 4; ++kk) {
            const uint32_t ko = kk * 32;
            uint32_t b[4][4];
#pragma unroll
            for (int nb = 0; nb < 4; ++nb)
                ldm_x4(b[nb], aB[nb] + so + ko);
#pragma unroll
            for (int mt = 0; mt < 4; ++mt) {
                uint32_t a[4];
                ldm_x4(a, aA[mt] + so + ko);
#pragma unroll
                for (int nb = 0; nb < 4; ++nb) {
                    mma_f16(acc[mt][2 * nb],     a, b[nb]);
                    mma_f16(acc[mt][2 * nb + 1], a, b[nb] + 2);
                }
            }
        }
        __syncthreads();
    }

    // ---- epilogue: fp16 store + BN-stat accumulation ----
    const int cb = (lane & 3) * 2;
#pragma unroll
    for (int mt = 0; mt < 4; ++mt) {
        int r0 = row0 + m0 + mt * 16 + (lane >> 2);
        int r1 = r0 + 8;
        if (r0 < N) {
            __half* o = g_out1h + (size_t)r0 * D + cb;
#pragma unroll
            for (int nt = 0; nt < 8; ++nt)
                *(__half2*)(o + nt * 8) = __floats2half2_rn(acc[mt][nt][0], acc[mt][nt][1]);
        }
        if (r1 < N) {
            __half* o = g_out1h + (size_t)r1 * D + cb;
#pragma unroll
            for (int nt = 0; nt < 8; ++nt)
                *(__half2*)(o + nt * 8) = __floats2half2_rn(acc[mt][nt][2], acc[mt][nt][3]);
        }
    }
    // stats: pad rows hold exact zeros -> safe unmasked
#pragma unroll
    for (int nt = 0; nt < 8; ++nt) {
        float cs0 = 0.f, cq0 = 0.f, cs1 = 0.f, cq1 = 0.f;
#pragma unroll
        for (int mt = 0; mt < 4; ++mt) {
            float a0 = acc[mt][nt][0], a2 = acc[mt][nt][2];
            float a1 = acc[mt][nt][1], a3 = acc[mt][nt][3];
            cs0 += a0 + a2; cq0 += a0 * a0 + a2 * a2;
            cs1 += a1 + a3; cq1 += a1 * a1 + a3 * a3;
        }
        atomicAdd(&s_sum[cb + nt * 8 + 0], cs0);
        atomicAdd(&s_sq [cb + nt * 8 + 0], cq0);
        atomicAdd(&s_sum[cb + nt * 8 + 1], cs1);
        atomicAdd(&s_sq [cb + nt * 8 + 1], cq1);
    }
    __syncthreads();
    if (tid < D) {
        atomicAdd(&g_sum[tid], s_sum[tid]);
        atomicAdd(&g_sq [tid], s_sq[tid]);
    }
}

// ============================================================
// finalize (parallel): BN -> fold into W2 (fp16) + bias vector
// ============================================================
__global__ __launch_bounds__(64) void finalize_kernel(
    const float* __restrict__ gamma,
    const float* __restrict__ beta,
    const float* __restrict__ W2,
    float invN)
{
    __shared__ float red[2];
    const int c = threadIdx.x;   // input channel
    const int n = blockIdx.x;    // W2 output column
    float mean = g_sum[c] * invN;
    float var  = g_sq[c] * invN - mean * mean;
    float rstd = rsqrtf(var + 1e-5f);
    float sc   = rstd * gamma[c];
    float sh   = beta[c] - mean * sc;
    float w = W2[(size_t)c * 256 + n];
    g_W2h[n * 64 + c] = __float2half_rn(sc * w);
    float b = sh * w;
#pragma unroll
    for (int off = 16; off; off >>= 1) b += __shfl_down_sync(~0u, b, off);
    if ((c & 31) == 0) red[c >> 5] = b;
    __syncthreads();
    if (c == 0) g_bias[n] = red[0] + red[1];
}

// ============================================================
// fused MLP via mma.sync fp16: 128-row tile, 4 warps,
// warp tile 32x64. GEMM1 accumulators re-packed IN REGISTERS
// as GEMM2's A fragments. out = relu(out1h @ W2' + bias) @ W3 + x
// ============================================================
__global__ __launch_bounds__(128) void mlp_mma_kernel(
    const float* __restrict__ x,
    float* __restrict__ out,
    int N)
{
    extern __shared__ __align__(16) __half sm[];
    __half* Ah  = sm;                     // 128*72
    __half* W2s = Ah + 128 * ASTRIDE;     // 64*72
    __half* W3s = W2s + 64 * ASTRIDE;     // 64*72
    __shared__ float s_bias[256];

    const int tid  = threadIdx.x;         // 0..127
    const int wid  = tid >> 5;            // 0..3
    const int lane = tid & 31;
    const int row0 = blockIdx.x * 128;

    s_bias[tid] = g_bias[tid];
    s_bias[tid + 128] = g_bias[tid + 128];

    // ---- A tile: chunk-parallel coalesced load ----
    {
        const int grp = lane >> 3;
        const int ch  = lane & 7;
#pragma unroll
        for (int i = 0; i < 8; ++i) {
            int lrow = (wid << 5) + (i << 2) + grp;
            int row = row0 + lrow;
            uint4 v = make_uint4(0, 0, 0, 0);
            if (row < N)
                v = *((const uint4*)(g_out1h + (size_t)row * D) + ch);
            *(uint4*)((char*)Ah + lrow * ASTRIDE * 2 + ch * 16) = v;
        }
    }

    const int m0 = wid * 32;

    const uint32_t uAh  = smem_u32(Ah);
    const uint32_t uW2s = smem_u32(W2s);
    const uint32_t uW3s = smem_u32(W3s);
    uint32_t oA[2];
#pragma unroll
    for (int mt = 0; mt < 2; ++mt)
        oA[mt] = (uint32_t)(((m0 + mt * 16 + (lane & 15)) * ASTRIDE + (lane >> 4) * 8) * 2);
    uint32_t oB[4];
#pragma unroll
    for (int nb = 0; nb < 4; ++nb)
        oB[nb] = (uint32_t)(((nb * 16 + (lane & 7) + ((lane >> 4) << 3)) * ASTRIDE
                             + ((lane >> 3) & 1) * 8) * 2);

    float acc2[2][8][4];
#pragma unroll
    for (int mt = 0; mt < 2; ++mt)
#pragma unroll
        for (int nt = 0; nt < 8; ++nt)
#pragma unroll
            for (int e = 0; e < 4; ++e) acc2[mt][nt][e] = 0.f;

    const int ccol = (lane & 3) * 2;

    for (int cb4 = 0; cb4 < 4; ++cb4) {
        const int c0 = cb4 * 64;

        // ---- load W2' chunk + W3 chunk (8KB each) ----
        {
            const uint4* sh2 = (const uint4*)(g_W2h + (size_t)c0 * 64);
#pragma unroll
            for (int j = 0; j < 4; ++j) {
                int f = tid + 128 * j;
                *(uint4*)((char*)(W2s + (f >> 3) * ASTRIDE) + (f & 7) * 16) = sh2[f];
                *(uint4*)((char*)(W3s + (f >> 3) * ASTRIDE) + (f & 7) * 16) =
                    *((const uint4*)(g_W3h + (size_t)(f >> 3) * 256 + c0) + (f & 7));
            }
        }
        __syncthreads();

        // ---- GEMM1 chunk: acc1 = A @ W2'c + bias ----
        float acc1[2][8][4];
#pragma unroll
        for (int mt = 0; mt < 2; ++mt)
#pragma unroll
            for (int nt = 0; nt < 8; ++nt) {
                float b0 = s_bias[c0 + nt * 8 + ccol];
                float b1 = s_bias[c0 + nt * 8 + ccol + 1];
                acc1[mt][nt][0] = b0; acc1[mt][nt][1] = b1;
                acc1[mt][nt][2] = b0; acc1[mt][nt][3] = b1;
            }

#pragma unroll
        for (int kk = 0; kk < 4; ++kk) {
            const uint32_t ko = kk * 32;
            uint32_t b[4][4];
#pragma unroll
            for (int nb = 0; nb < 4; ++nb)
                ldm_x4(b[nb], uW2s + oB[nb] + ko);
#pragma unroll
            for (int mt = 0; mt < 2; ++mt) {
                uint32_t a[4];
                ldm_x4(a, uAh + oA[mt] + ko);
#pragma unroll
                for (int nb = 0; nb < 4; ++nb) {
                    mma_f16(acc1[mt][2 * nb],     a, b[nb]);
                    mma_f16(acc1[mt][2 * nb + 1], a, b[nb] + 2);
                }
            }
        }

        // ---- relu + pack acc1 -> GEMM2 A fragments (registers only) ----
        uint32_t af[2][4][4];
#pragma unroll
        for (int mt = 0; mt < 2; ++mt)
#pragma unroll
            for (int kt = 0; kt < 4; ++kt) {
                af[mt][kt][0] = relu_h2(acc1[mt][2 * kt][0],     acc1[mt][2 * kt][1]);
                af[mt][kt][1] = relu_h2(acc1[mt][2 * kt][2],     acc1[mt][2 * kt][3]);
                af[mt][kt][2] = relu_h2(acc1[mt][2 * kt + 1][0], acc1[mt][2 * kt + 1][1]);
                af[mt][kt][3] = relu_h2(acc1[mt][2 * kt + 1][2], acc1[mt][2 * kt + 1][3]);
            }

        // ---- GEMM2 chunk: acc2 += relu(T) @ W3c, A from registers ----
#pragma unroll
        for (int kt = 0; kt < 4; ++kt) {
            const uint32_t ko = kt * 32;
            uint32_t b[4][4];
#pragma unroll
            for (int nb = 0; nb < 4; ++nb)
                ldm_x4(b[nb], uW3s + oB[nb] + ko);
#pragma unroll
            for (int mt = 0; mt < 2; ++mt) {
#pragma unroll
                for (int nb = 0; nb < 4; ++nb) {
                    mma_f16(acc2[mt][2 * nb],     af[mt][kt], b[nb]);
                    mma_f16(acc2[mt][2 * nb + 1], af[mt][kt], b[nb] + 2);
                }
            }
        }
        __syncthreads();   // all warps done with W2s/W3s before refill
    }

    // ---- epilogue: residual + store ----
#pragma unroll
    for (int mt = 0; mt < 2; ++mt) {
        int r0 = row0 + m0 + mt * 16 + (lane >> 2);
        int r1 = r0 + 8;
        if (r0 < N) {
            float* o = out + (size_t)r0 * D + ccol;
            const float* xr = x + (size_t)r0 * D + ccol;
#pragma unroll
            for (int nt = 0; nt < 8; ++nt) {
                float2 xv = *(const float2*)(xr + nt * 8);
                *(float2*)(o + nt * 8) =
                    make_float2(acc2[mt][nt][0] + xv.x, acc2[mt][nt][1] + xv.y);
            }
        }
        if (r1 < N) {
            float* o = out + (size_t)r1 * D + ccol;
            const float* xr = x + (size_t)r1 * D + ccol;
#pragma unroll
            for (int nt = 0; nt < 8; ++nt) {
                float2 xv = *(const float2*)(xr + nt * 8);
                *(float2*)(o + nt * 8) =
                    make_float2(acc2[mt][nt][2] + xv.x, acc2[mt][nt][3] + xv.y);
            }
        }
    }
}

// ============================================================
// launch
// ============================================================
extern "C" void kernel_launch(void* const* d_in, const int* in_sizes, int n_in,
                              void* d_out, int out_size)
{
    const float* x     = (const float*)d_in[0];
    const int*   nidx  = (const int*)  d_in[1];
    const int*   nmask = (const int*)  d_in[2];
    const float* W1    = (const float*)d_in[3];
    const float* gamma = (const float*)d_in[4];
    const float* beta  = (const float*)d_in[5];
    const float* W2    = (const float*)d_in[6];
    const float* W3    = (const float*)d_in[7];
    float* out = (float*)d_out;

    const int N = in_sizes[0] / D;
    const int K = in_sizes[1] / N;

    const int conv_smem = STAGE_HALVES * 2 * 2;                      // 2 stages
    cudaFuncSetAttribute(conv1_mma_kernel, cudaFuncAttributeMaxDynamicSharedMemorySize, conv_smem);
    const int mlp_smem = (128 * ASTRIDE + 64 * ASTRIDE * 2) * 2;     // A + W2 + W3
    cudaFuncSetAttribute(mlp_mma_kernel, cudaFuncAttributeMaxDynamicSharedMemorySize, mlp_smem);

    const int total8 = N * D / 8;
    prep_kernel<<<(total8 + 255) / 256, 256>>>(x, W1, W3, total8, K);
    conv1_mma_kernel<<<(N + 255) / 256, 128, conv_smem>>>(nidx, nmask, N, K);
    finalize_kernel<<<256, 64>>>(gamma, beta, W2, 1.0f / (float)N);
    mlp_mma_kernel<<<(N + 127) / 128, 128, mlp_smem>>>(x, out, N);
}

// round 13
// speedup vs baseline: 1.5460x; 1.5460x over previous
#include <cuda_runtime.h>
#include <cuda_fp16.h>
#include <cstdint>

#define D 64
#define MAXN 150208
#define KMAX 27
#define ASTRIDE 72

// ---- scratch (static device arrays: allocation-free) ----
__device__ __half g_out1h[(size_t)MAXN * D];  // conv1 output (fp16)
__device__ float g_sum[D];
__device__ float g_sq[D];
__device__ float g_bias[256];                 // sh @ W2
__device__ __half g_xh[(size_t)MAXN * D];     // x rounded to fp16
__device__ __half g_W1h[(size_t)KMAX * 4096]; // W1^T [k][n][c] fp16
__device__ __half g_W2h[256 * 64];            // (sc*W2)^T [n][c] fp16 (post-BN fold)
__device__ __half g_W3h[64 * 256];            // W3^T [n][c] fp16

// ============================================================
// helpers
// ============================================================
__device__ __forceinline__ uint32_t smem_u32(const void* p) {
    uint32_t a;
    asm("{ .reg .u64 t; cvta.to.shared.u64 t, %1; cvt.u32.u64 %0, t; }" : "=r"(a) : "l"(p));
    return a;
}

__device__ __forceinline__ void ldm_x4(uint32_t* r, uint32_t addr) {
    asm volatile("ldmatrix.sync.aligned.m8n8.x4.shared.b16 {%0,%1,%2,%3}, [%4];"
                 : "=r"(r[0]), "=r"(r[1]), "=r"(r[2]), "=r"(r[3]) : "r"(addr));
}

__device__ __forceinline__ void mma_f16(float* d, const uint32_t* a, const uint32_t* b) {
    asm volatile(
        "mma.sync.aligned.m16n8k16.row.col.f32.f16.f16.f32 "
        "{%0,%1,%2,%3},{%4,%5,%6,%7},{%8,%9},{%0,%1,%2,%3};"
        : "+f"(d[0]), "+f"(d[1]), "+f"(d[2]), "+f"(d[3])
        : "r"(a[0]), "r"(a[1]), "r"(a[2]), "r"(a[3]), "r"(b[0]), "r"(b[1]));
}

__device__ __forceinline__ void cpa16(uint32_t dst, const void* src, uint32_t sz) {
    asm volatile("cp.async.cg.shared.global [%0], [%1], 16, %2;"
                 :: "r"(dst), "l"(src), "r"(sz) : "memory");
}
#define CPA_COMMIT() asm volatile("cp.async.commit_group;" ::: "memory")
#define CPA_WAIT0()  asm volatile("cp.async.wait_group 0;" ::: "memory")
#define CPA_WAIT1()  asm volatile("cp.async.wait_group 1;" ::: "memory")

__device__ __forceinline__ uint32_t relu_h2(float a, float b) {
    __half2 h = __floats2half2_rn(fmaxf(a, 0.f), fmaxf(b, 0.f));
    return *(uint32_t*)&h;
}

// ============================================================
// prep (single kernel): x->fp16, W1^T fp16, W3^T fp16, zero stats
// ============================================================
__global__ void prep_kernel(const float* __restrict__ x,
                            const float* __restrict__ W1,
                            const float* __restrict__ W3,
                            int total8, int K) {
    const int tid = threadIdx.x;
    if (blockIdx.x == 0) {
        if (tid < D) { g_sum[tid] = 0.f; g_sq[tid] = 0.f; }
        for (int e = tid; e < 64 * 256; e += blockDim.x) {
            int n = e >> 8, c = e & 255;
            g_W3h[n * 256 + c] = __float2half_rn(W3[(size_t)c * 64 + n]);
        }
    }
    if (blockIdx.x < (unsigned)K) {
        const float* Wk = W1 + (size_t)blockIdx.x * 4096;
        __half* dh = g_W1h + (size_t)blockIdx.x * 4096;
        for (int e = tid; e < 4096; e += blockDim.x) {
            int n = e >> 6, c = e & 63;
            dh[n * 64 + c] = __float2half_rn(Wk[c * 64 + n]);
        }
    }
    int e = blockIdx.x * blockDim.x + tid;
    if (e >= total8) return;
    const float4* s = (const float4*)x + 2 * e;
    float4 a = s[0], b = s[1];
    uint4 o;
    __half2 h;
    h = __floats2half2_rn(a.x, a.y); o.x = *(uint32_t*)&h;
    h = __floats2half2_rn(a.z, a.w); o.y = *(uint32_t*)&h;
    h = __floats2half2_rn(b.x, b.y); o.z = *(uint32_t*)&h;
    h = __floats2half2_rn(b.z, b.w); o.w = *(uint32_t*)&h;
    ((uint4*)g_xh)[e] = o;
}

// ============================================================
// conv1 via mma.sync fp16: 256x64 tile per CTA, 4 warps,
// warp tile 64x64. Double-buffered cp.async pipeline.
// Gather: idx staged through smem (2 LDG/thread/k), then
// chunk-parallel coalesced cp.async (full 128B lines).
// ============================================================
#define STAGE_HALVES ((256 + 64) * ASTRIDE)   // A + W, halves per stage
__global__ __launch_bounds__(128, 2) void conv1_mma_kernel(
    const int*   __restrict__ nbr_idx,
    const int*   __restrict__ nbr_mask,
    int N, int K)
{
    extern __shared__ __align__(16) __half sm[];
    __shared__ float s_sum[D], s_sq[D];
    __shared__ int s_idx[2][256];

    const int tid  = threadIdx.x;         // 0..127
    const int wid  = tid >> 5;            // 0..3
    const int lane = tid & 31;
    const int row0 = blockIdx.x * 256;

    if (tid < D) { s_sum[tid] = 0.f; s_sq[tid] = 0.f; }

    const int gr0 = row0 + tid;
    const int gr1 = gr0 + 128;
    const uint32_t uBase = smem_u32(sm);
    const uint32_t stageB = STAGE_HALVES * 2;   // bytes per stage

    uint32_t wSm[4];
#pragma unroll
    for (int j = 0; j < 4; ++j) {
        int f = tid + 128 * j;
        wSm[j] = uBase + (uint32_t)(256 * ASTRIDE + (f >> 3) * ASTRIDE) * 2 + (f & 7) * 16;
    }

    const int m0 = wid * 64;
    uint32_t aA[4];
#pragma unroll
    for (int mt = 0; mt < 4; ++mt)
        aA[mt] = uBase + (uint32_t)(((m0 + mt * 16 + (lane & 15)) * ASTRIDE
                                     + (lane >> 4) * 8) * 2);
    uint32_t aB[4];
#pragma unroll
    for (int nb = 0; nb < 4; ++nb)
        aB[nb] = uBase + (uint32_t)((256 * ASTRIDE
                  + (nb * 16 + (lane & 7) + ((lane >> 4) << 3)) * ASTRIDE
                  + ((lane >> 3) & 1) * 8) * 2);

    float acc[4][8][4];
#pragma unroll
    for (int mt = 0; mt < 4; ++mt)
#pragma unroll
        for (int nt = 0; nt < 8; ++nt)
#pragma unroll
            for (int e = 0; e < 4; ++e) acc[mt][nt][e] = 0.f;

    const int grp = lane >> 3;   // row-in-quad 0..3
    const int ch  = lane & 7;    // 16B chunk 0..7

    // per-thread: 2 mask/idx LDGs -> smem (idx or -1)
    auto load_idx = [&](int k, int s) {
        const size_t kN = (size_t)k * N;
        int v0 = -1, v1 = -1;
        if (gr0 < N && nbr_mask[kN + gr0]) v0 = nbr_idx[kN + gr0];
        if (gr1 < N && nbr_mask[kN + gr1]) v1 = nbr_idx[kN + gr1];
        s_idx[s][tid] = v0;
        s_idx[s][tid + 128] = v1;
    };

    // coalesced cp.async from smem-staged indices (8-lane group per row)
    auto issue = [&](int k, int s) {
        const uint32_t so = (uint32_t)s * stageB;
        const char* wb = (const char*)(g_W1h + (size_t)k * 4096);
#pragma unroll
        for (int j = 0; j < 4; ++j)
            cpa16(wSm[j] + so, wb + (size_t)((tid + 128 * j) * 16), 16);
#pragma unroll
        for (int i = 0; i < 16; ++i) {
            int lrow = (wid << 6) + (i << 2) + grp;
            int idx = s_idx[s][lrow];                      // LDS broadcast
            int safe = idx < 0 ? 0 : idx;
            const char* src = (const char*)(g_xh + (size_t)safe * D) + ch * 16;
            uint32_t dst = uBase + so + (uint32_t)(lrow * ASTRIDE) * 2 + ch * 16;
            cpa16(dst, src, idx < 0 ? 0u : 16u);
        }
        CPA_COMMIT();
    };

    load_idx(0, 0);
    __syncthreads();
    issue(0, 0);

    for (int k = 0; k < K; ++k) {
        const int s = k & 1;
        if (k + 1 < K) load_idx(k + 1, s ^ 1);
        __syncthreads();                         // s_idx[s^1] visible
        if (k + 1 < K) { issue(k + 1, s ^ 1); CPA_WAIT1(); }
        else           { CPA_WAIT0(); }
        __syncthreads();                         // stage s complete for all warps

        const uint32_t so = (uint32_t)s * stageB;
#pragma unroll
        for (int kk = 0; kk < 4; ++kk) {
            const uint32_t ko = kk * 32;
            uint32_t b[4][4];
#pragma unroll
            for (int nb = 0; nb < 4; ++nb)
                ldm_x4(b[nb], aB[nb] + so + ko);
#pragma unroll
            for (int mt = 0; mt < 4; ++mt) {
                uint32_t a[4];
                ldm_x4(a, aA[mt] + so + ko);
#pragma unroll
                for (int nb = 0; nb < 4; ++nb) {
                    mma_f16(acc[mt][2 * nb],     a, b[nb]);
                    mma_f16(acc[mt][2 * nb + 1], a, b[nb] + 2);
                }
            }
        }
    }

    // ---- epilogue: fp16 store + BN-stat accumulation ----
    const int cb = (lane & 3) * 2;
#pragma unroll
    for (int mt = 0; mt < 4; ++mt) {
        int r0 = row0 + m0 + mt * 16 + (lane >> 2);
        int r1 = r0 + 8;
        if (r0 < N) {
            __half* o = g_out1h + (size_t)r0 * D + cb;
#pragma unroll
            for (int nt = 0; nt < 8; ++nt)
                *(__half2*)(o + nt * 8) = __floats2half2_rn(acc[mt][nt][0], acc[mt][nt][1]);
        }
        if (r1 < N) {
            __half* o = g_out1h + (size_t)r1 * D + cb;
#pragma unroll
            for (int nt = 0; nt < 8; ++nt)
                *(__half2*)(o + nt * 8) = __floats2half2_rn(acc[mt][nt][2], acc[mt][nt][3]);
        }
    }
    // stats: pad rows hold exact zeros -> safe unmasked
#pragma unroll
    for (int nt = 0; nt < 8; ++nt) {
        float cs0 = 0.f, cq0 = 0.f, cs1 = 0.f, cq1 = 0.f;
#pragma unroll
        for (int mt = 0; mt < 4; ++mt) {
            float a0 = acc[mt][nt][0], a2 = acc[mt][nt][2];
            float a1 = acc[mt][nt][1], a3 = acc[mt][nt][3];
            cs0 += a0 + a2; cq0 += a0 * a0 + a2 * a2;
            cs1 += a1 + a3; cq1 += a1 * a1 + a3 * a3;
        }
        atomicAdd(&s_sum[cb + nt * 8 + 0], cs0);
        atomicAdd(&s_sq [cb + nt * 8 + 0], cq0);
        atomicAdd(&s_sum[cb + nt * 8 + 1], cs1);
        atomicAdd(&s_sq [cb + nt * 8 + 1], cq1);
    }
    __syncthreads();
    if (tid < D) {
        atomicAdd(&g_sum[tid], s_sum[tid]);
        atomicAdd(&g_sq [tid], s_sq[tid]);
    }
}

// ============================================================
// finalize (parallel): BN -> fold into W2 (fp16) + bias vector
// ============================================================
__global__ __launch_bounds__(64) void finalize_kernel(
    const float* __restrict__ gamma,
    const float* __restrict__ beta,
    const float* __restrict__ W2,
    float invN)
{
    __shared__ float red[2];
    const int c = threadIdx.x;   // input channel
    const int n = blockIdx.x;    // W2 output column
    float mean = g_sum[c] * invN;
    float var  = g_sq[c] * invN - mean * mean;
    float rstd = rsqrtf(var + 1e-5f);
    float sc   = rstd * gamma[c];
    float sh   = beta[c] - mean * sc;
    float w = W2[(size_t)c * 256 + n];
    g_W2h[n * 64 + c] = __float2half_rn(sc * w);
    float b = sh * w;
#pragma unroll
    for (int off = 16; off; off >>= 1) b += __shfl_down_sync(~0u, b, off);
    if ((c & 31) == 0) red[c >> 5] = b;
    __syncthreads();
    if (c == 0) g_bias[n] = red[0] + red[1];
}

// ============================================================
// fused MLP via mma.sync fp16: 128-row tile, 4 warps,
// warp tile 32x64. GEMM1 accumulators re-packed IN REGISTERS
// as GEMM2's A fragments. out = relu(out1h @ W2' + bias) @ W3 + x
// ============================================================
__global__ __launch_bounds__(128) void mlp_mma_kernel(
    const float* __restrict__ x,
    float* __restrict__ out,
    int N)
{
    extern __shared__ __align__(16) __half sm[];
    __half* Ah  = sm;                     // 128*72
    __half* W2s = Ah + 128 * ASTRIDE;     // 64*72
    __half* W3s = W2s + 64 * ASTRIDE;     // 64*72
    __shared__ float s_bias[256];

    const int tid  = threadIdx.x;         // 0..127
    const int wid  = tid >> 5;            // 0..3
    const int lane = tid & 31;
    const int row0 = blockIdx.x * 128;

    s_bias[tid] = g_bias[tid];
    s_bias[tid + 128] = g_bias[tid + 128];

    // ---- A tile: chunk-parallel coalesced load (rows contiguous) ----
    {
        const int grp = lane >> 3;
        const int ch  = lane & 7;
#pragma unroll
        for (int i = 0; i < 8; ++i) {
            int lrow = (wid << 5) + (i << 2) + grp;
            int row = row0 + lrow;
            uint4 v = make_uint4(0, 0, 0, 0);
            if (row < N)
                v = *((const uint4*)(g_out1h + (size_t)row * D) + ch);
            *(uint4*)((char*)Ah + lrow * ASTRIDE * 2 + ch * 16) = v;
        }
    }

    const int m0 = wid * 32;

    const uint32_t uAh  = smem_u32(Ah);
    const uint32_t uW2s = smem_u32(W2s);
    const uint32_t uW3s = smem_u32(W3s);
    uint32_t oA[2];
#pragma unroll
    for (int mt = 0; mt < 2; ++mt)
        oA[mt] = (uint32_t)(((m0 + mt * 16 + (lane & 15)) * ASTRIDE + (lane >> 4) * 8) * 2);
    uint32_t oB[4];
#pragma unroll
    for (int nb = 0; nb < 4; ++nb)
        oB[nb] = (uint32_t)(((nb * 16 + (lane & 7) + ((lane >> 4) << 3)) * ASTRIDE
                             + ((lane >> 3) & 1) * 8) * 2);

    float acc2[2][8][4];
#pragma unroll
    for (int mt = 0; mt < 2; ++mt)
#pragma unroll
        for (int nt = 0; nt < 8; ++nt)
#pragma unroll
            for (int e = 0; e < 4; ++e) acc2[mt][nt][e] = 0.f;

    const int ccol = (lane & 3) * 2;

    for (int cb4 = 0; cb4 < 4; ++cb4) {
        const int c0 = cb4 * 64;

        // ---- load W2' chunk + W3 chunk (8KB each) ----
        {
            const uint4* sh2 = (const uint4*)(g_W2h + (size_t)c0 * 64);
#pragma unroll
            for (int j = 0; j < 4; ++j) {
                int f = tid + 128 * j;
                *(uint4*)((char*)(W2s + (f >> 3) * ASTRIDE) + (f & 7) * 16) = sh2[f];
                *(uint4*)((char*)(W3s + (f >> 3) * ASTRIDE) + (f & 7) * 16) =
                    *((const uint4*)(g_W3h + (size_t)(f >> 3) * 256 + c0) + (f & 7));
            }
        }
        __syncthreads();

        // ---- GEMM1 chunk: acc1 = A @ W2'c + bias ----
        float acc1[2][8][4];
#pragma unroll
        for (int mt = 0; mt < 2; ++mt)
#pragma unroll
            for (int nt = 0; nt < 8; ++nt) {
                float b0 = s_bias[c0 + nt * 8 + ccol];
                float b1 = s_bias[c0 + nt * 8 + ccol + 1];
                acc1[mt][nt][0] = b0; acc1[mt][nt][1] = b1;
                acc1[mt][nt][2] = b0; acc1[mt][nt][3] = b1;
            }

#pragma unroll
        for (int kk = 0; kk < 4; ++kk) {
            const uint32_t ko = kk * 32;
            uint32_t b[4][4];
#pragma unroll
            for (int nb = 0; nb < 4; ++nb)
                ldm_x4(b[nb], uW2s + oB[nb] + ko);
#pragma unroll
            for (int mt = 0; mt < 2; ++mt) {
                uint32_t a[4];
                ldm_x4(a, uAh + oA[mt] + ko);
#pragma unroll
                for (int nb = 0; nb < 4; ++nb) {
                    mma_f16(acc1[mt][2 * nb],     a, b[nb]);
                    mma_f16(acc1[mt][2 * nb + 1], a, b[nb] + 2);
                }
            }
        }

        // ---- relu + pack acc1 -> GEMM2 A fragments (registers only) ----
        uint32_t af[2][4][4];
#pragma unroll
        for (int mt = 0; mt < 2; ++mt)
#pragma unroll
            for (int kt = 0; kt < 4; ++kt) {
                af[mt][kt][0] = relu_h2(acc1[mt][2 * kt][0],     acc1[mt][2 * kt][1]);
                af[mt][kt][1] = relu_h2(acc1[mt][2 * kt][2],     acc1[mt][2 * kt][3]);
                af[mt][kt][2] = relu_h2(acc1[mt][2 * kt + 1][0], acc1[mt][2 * kt + 1][1]);
                af[mt][kt][3] = relu_h2(acc1[mt][2 * kt + 1][2], acc1[mt][2 * kt + 1][3]);
            }

        // ---- GEMM2 chunk: acc2 += relu(T) @ W3c, A from registers ----
#pragma unroll
        for (int kt = 0; kt < 4; ++kt) {
            const uint32_t ko = kt * 32;
            uint32_t b[4][4];
#pragma unroll
            for (int nb = 0; nb < 4; ++nb)
                ldm_x4(b[nb], uW3s + oB[nb] + ko);
#pragma unroll
            for (int mt = 0; mt < 2; ++mt) {
#pragma unroll
                for (int nb = 0; nb < 4; ++nb) {
                    mma_f16(acc2[mt][2 * nb],     af[mt][kt], b[nb]);
                    mma_f16(acc2[mt][2 * nb + 1], af[mt][kt], b[nb] + 2);
                }
            }
        }
        __syncthreads();   // all warps done with W2s/W3s before refill
    }

    // ---- epilogue: residual + store ----
#pragma unroll
    for (int mt = 0; mt < 2; ++mt) {
        int r0 = row0 + m0 + mt * 16 + (lane >> 2);
        int r1 = r0 + 8;
        if (r0 < N) {
            float* o = out + (size_t)r0 * D + ccol;
            const float* xr = x + (size_t)r0 * D + ccol;
#pragma unroll
            for (int nt = 0; nt < 8; ++nt) {
                float2 xv = *(const float2*)(xr + nt * 8);
                *(float2*)(o + nt * 8) =
                    make_float2(acc2[mt][nt][0] + xv.x, acc2[mt][nt][1] + xv.y);
            }
        }
        if (r1 < N) {
            float* o = out + (size_t)r1 * D + ccol;
            const float* xr = x + (size_t)r1 * D + ccol;
#pragma unroll
            for (int nt = 0; nt < 8; ++nt) {
                float2 xv = *(const float2*)(xr + nt * 8);
                *(float2*)(o + nt * 8) =
                    make_float2(acc2[mt][nt][2] + xv.x, acc2[mt][nt][3] + xv.y);
            }
        }
    }
}

// ============================================================
// launch
// ============================================================
extern "C" void kernel_launch(void* const* d_in, const int* in_sizes, int n_in,
                              void* d_out, int out_size)
{
    const float* x     = (const float*)d_in[0];
    const int*   nidx  = (const int*)  d_in[1];
    const int*   nmask = (const int*)  d_in[2];
    const float* W1    = (const float*)d_in[3];
    const float* gamma = (const float*)d_in[4];
    const float* beta  = (const float*)d_in[5];
    const float* W2    = (const float*)d_in[6];
    const float* W3    = (const float*)d_in[7];
    float* out = (float*)d_out;

    const int N = in_sizes[0] / D;
    const int K = in_sizes[1] / N;

    const int conv_smem = STAGE_HALVES * 2 * 2;                      // 2 stages
    cudaFuncSetAttribute(conv1_mma_kernel, cudaFuncAttributeMaxDynamicSharedMemorySize, conv_smem);
    const int mlp_smem = (128 * ASTRIDE + 64 * ASTRIDE * 2) * 2;     // A + W2 + W3
    cudaFuncSetAttribute(mlp_mma_kernel, cudaFuncAttributeMaxDynamicSharedMemorySize, mlp_smem);

    const int total8 = N * D / 8;
    prep_kernel<<<(total8 + 255) / 256, 256>>>(x, W1, W3, total8, K);
    conv1_mma_kernel<<<(N + 255) / 256, 128, conv_smem>>>(nidx, nmask, N, K);
    finalize_kernel<<<256, 64>>>(gamma, beta, W2, 1.0f / (float)N);
    mlp_mma_kernel<<<(N + 127) / 128, 128, mlp_smem>>>(x, out, N);
}

// round 14
// speedup vs baseline: 1.6817x; 1.0877x over previous
#include <cuda_runtime.h>
#include <cuda_fp16.h>
#include <cstdint>

#define D 64
#define MAXN 150208
#define KMAX 27
#define ASTRIDE 72

// ---- scratch (static device arrays: allocation-free) ----
__device__ __half g_out1h[(size_t)MAXN * D];  // conv1 output (fp16)
__device__ float g_sum[D];
__device__ float g_sq[D];
__device__ float g_bias[256];                 // sh @ W2
__device__ __half g_xh[(size_t)MAXN * D];     // x rounded to fp16
__device__ __half g_W1h[(size_t)KMAX * 4096]; // W1^T [k][n][c] fp16
__device__ __half g_W2h[256 * 64];            // (sc*W2)^T [n][c] fp16 (post-BN fold)
__device__ __half g_W3h[64 * 256];            // W3^T [n][c] fp16

// ============================================================
// helpers
// ============================================================
__device__ __forceinline__ uint32_t smem_u32(const void* p) {
    uint32_t a;
    asm("{ .reg .u64 t; cvta.to.shared.u64 t, %1; cvt.u32.u64 %0, t; }" : "=r"(a) : "l"(p));
    return a;
}

__device__ __forceinline__ void ldm_x4(uint32_t* r, uint32_t addr) {
    asm volatile("ldmatrix.sync.aligned.m8n8.x4.shared.b16 {%0,%1,%2,%3}, [%4];"
                 : "=r"(r[0]), "=r"(r[1]), "=r"(r[2]), "=r"(r[3]) : "r"(addr));
}

__device__ __forceinline__ void mma_f16(float* d, const uint32_t* a, const uint32_t* b) {
    asm volatile(
        "mma.sync.aligned.m16n8k16.row.col.f32.f16.f16.f32 "
        "{%0,%1,%2,%3},{%4,%5,%6,%7},{%8,%9},{%0,%1,%2,%3};"
        : "+f"(d[0]), "+f"(d[1]), "+f"(d[2]), "+f"(d[3])
        : "r"(a[0]), "r"(a[1]), "r"(a[2]), "r"(a[3]), "r"(b[0]), "r"(b[1]));
}

__device__ __forceinline__ void cpa16(uint32_t dst, const void* src, uint32_t sz) {
    asm volatile("cp.async.cg.shared.global [%0], [%1], 16, %2;"
                 :: "r"(dst), "l"(src), "r"(sz) : "memory");
}
#define CPA_COMMIT() asm volatile("cp.async.commit_group;" ::: "memory")
#define CPA_WAIT0()  asm volatile("cp.async.wait_group 0;" ::: "memory")
#define CPA_WAIT1()  asm volatile("cp.async.wait_group 1;" ::: "memory")

__device__ __forceinline__ uint32_t relu_h2(float a, float b) {
    __half2 h = __floats2half2_rn(fmaxf(a, 0.f), fmaxf(b, 0.f));
    return *(uint32_t*)&h;
}

// ============================================================
// prep (single kernel): x->fp16, W1^T fp16, W3^T fp16, zero stats
// ============================================================
__global__ void prep_kernel(const float* __restrict__ x,
                            const float* __restrict__ W1,
                            const float* __restrict__ W3,
                            int total8, int K) {
    const int tid = threadIdx.x;
    if (blockIdx.x == 0) {
        if (tid < D) { g_sum[tid] = 0.f; g_sq[tid] = 0.f; }
        for (int e = tid; e < 64 * 256; e += blockDim.x) {
            int n = e >> 8, c = e & 255;
            g_W3h[n * 256 + c] = __float2half_rn(W3[(size_t)c * 64 + n]);
        }
    }
    if (blockIdx.x < (unsigned)K) {
        const float* Wk = W1 + (size_t)blockIdx.x * 4096;
        __half* dh = g_W1h + (size_t)blockIdx.x * 4096;
        for (int e = tid; e < 4096; e += blockDim.x) {
            int n = e >> 6, c = e & 63;
            dh[n * 64 + c] = __float2half_rn(Wk[c * 64 + n]);
        }
    }
    int e = blockIdx.x * blockDim.x + tid;
    if (e >= total8) return;
    const float4* s = (const float4*)x + 2 * e;
    float4 a = s[0], b = s[1];
    uint4 o;
    __half2 h;
    h = __floats2half2_rn(a.x, a.y); o.x = *(uint32_t*)&h;
    h = __floats2half2_rn(a.z, a.w); o.y = *(uint32_t*)&h;
    h = __floats2half2_rn(b.x, b.y); o.z = *(uint32_t*)&h;
    h = __floats2half2_rn(b.z, b.w); o.w = *(uint32_t*)&h;
    ((uint4*)g_xh)[e] = o;
}

// ============================================================
// conv1 via mma.sync fp16: 128x64 tile per CTA, 4 warps,
// warp tile 32x64. Double-buffered cp.async pipeline.
// High occupancy: 4 CTAs/SM (16 warps) for latency hiding.
// ============================================================
#define STAGE_HALVES ((128 + 64) * ASTRIDE)   // A + W, halves per stage
__global__ __launch_bounds__(128, 4) void conv1_mma_kernel(
    const int*   __restrict__ nbr_idx,
    const int*   __restrict__ nbr_mask,
    int N, int K)
{
    extern __shared__ __align__(16) __half sm[];
    __shared__ float s_sum[D], s_sq[D];

    const int tid  = threadIdx.x;         // 0..127
    const int wid  = tid >> 5;            // 0..3
    const int lane = tid & 31;
    const int row0 = blockIdx.x * 128;

    if (tid < D) { s_sum[tid] = 0.f; s_sq[tid] = 0.f; }

    const int grow = row0 + tid;          // 1 row per thread
    const uint32_t uBase = smem_u32(sm);
    const uint32_t stageB = STAGE_HALVES * 2;   // bytes per stage

    const uint32_t aSm = uBase + (uint32_t)(tid * ASTRIDE) * 2;
    uint32_t wSm[4];
#pragma unroll
    for (int j = 0; j < 4; ++j) {
        int f = tid + 128 * j;
        wSm[j] = uBase + (uint32_t)(128 * ASTRIDE + (f >> 3) * ASTRIDE) * 2 + (f & 7) * 16;
    }

    const int m0 = wid * 32;
    uint32_t aA[2];
#pragma unroll
    for (int mt = 0; mt < 2; ++mt)
        aA[mt] = uBase + (uint32_t)(((m0 + mt * 16 + (lane & 15)) * ASTRIDE
                                     + (lane >> 4) * 8) * 2);
    uint32_t aB[4];
#pragma unroll
    for (int nb = 0; nb < 4; ++nb)
        aB[nb] = uBase + (uint32_t)((128 * ASTRIDE
                  + (nb * 16 + (lane & 7) + ((lane >> 4) << 3)) * ASTRIDE
                  + ((lane >> 3) & 1) * 8) * 2);

    float acc[2][8][4];
#pragma unroll
    for (int mt = 0; mt < 2; ++mt)
#pragma unroll
        for (int nt = 0; nt < 8; ++nt)
#pragma unroll
            for (int e = 0; e < 4; ++e) acc[mt][nt][e] = 0.f;

    auto issue = [&](int k, int s) {
        const uint32_t so = (uint32_t)s * stageB;
        const char* wb = (const char*)(g_W1h + (size_t)k * 4096);
#pragma unroll
        for (int j = 0; j < 4; ++j)
            cpa16(wSm[j] + so, wb + (size_t)((tid + 128 * j) * 16), 16);
        int m = 0, idx = 0;
        if (grow < N) {
            m = nbr_mask[(size_t)k * N + grow];
            if (m) idx = nbr_idx[(size_t)k * N + grow];
        }
        const char* src = (const char*)(g_xh + (size_t)idx * D);
        uint32_t z = m ? 16u : 0u;
#pragma unroll
        for (int j = 0; j < 8; ++j)
            cpa16(aSm + so + j * 16, src + j * 16, z);
        CPA_COMMIT();
    };

    issue(0, 0);

    for (int k = 0; k < K; ++k) {
        const int s = k & 1;
        if (k + 1 < K) { issue(k + 1, s ^ 1); CPA_WAIT1(); }
        else           { CPA_WAIT0(); }
        __syncthreads();

        const uint32_t so = (uint32_t)s * stageB;
#pragma unroll
        for (int kk = 0; kk < 4; ++kk) {
            const uint32_t ko = kk * 32;
            uint32_t b[4][4];
#pragma unroll
            for (int nb = 0; nb < 4; ++nb)
                ldm_x4(b[nb], aB[nb] + so + ko);
#pragma unroll
            for (int mt = 0; mt < 2; ++mt) {
                uint32_t a[4];
                ldm_x4(a, aA[mt] + so + ko);
#pragma unroll
                for (int nb = 0; nb < 4; ++nb) {
                    mma_f16(acc[mt][2 * nb],     a, b[nb]);
                    mma_f16(acc[mt][2 * nb + 1], a, b[nb] + 2);
                }
            }
        }
        __syncthreads();   // all warps done with stage s before refill
    }

    // ---- epilogue: fp16 store + BN-stat accumulation ----
    const int cb = (lane & 3) * 2;
#pragma unroll
    for (int mt = 0; mt < 2; ++mt) {
        int r0 = row0 + m0 + mt * 16 + (lane >> 2);
        int r1 = r0 + 8;
        if (r0 < N) {
            __half* o = g_out1h + (size_t)r0 * D + cb;
#pragma unroll
            for (int nt = 0; nt < 8; ++nt)
                *(__half2*)(o + nt * 8) = __floats2half2_rn(acc[mt][nt][0], acc[mt][nt][1]);
        }
        if (r1 < N) {
            __half* o = g_out1h + (size_t)r1 * D + cb;
#pragma unroll
            for (int nt = 0; nt < 8; ++nt)
                *(__half2*)(o + nt * 8) = __floats2half2_rn(acc[mt][nt][2], acc[mt][nt][3]);
        }
    }
    // stats: pad rows hold exact zeros -> safe unmasked
#pragma unroll
    for (int nt = 0; nt < 8; ++nt) {
        float cs0 = 0.f, cq0 = 0.f, cs1 = 0.f, cq1 = 0.f;
#pragma unroll
        for (int mt = 0; mt < 2; ++mt) {
            float a0 = acc[mt][nt][0], a2 = acc[mt][nt][2];
            float a1 = acc[mt][nt][1], a3 = acc[mt][nt][3];
            cs0 += a0 + a2; cq0 += a0 * a0 + a2 * a2;
            cs1 += a1 + a3; cq1 += a1 * a1 + a3 * a3;
        }
        atomicAdd(&s_sum[cb + nt * 8 + 0], cs0);
        atomicAdd(&s_sq [cb + nt * 8 + 0], cq0);
        atomicAdd(&s_sum[cb + nt * 8 + 1], cs1);
        atomicAdd(&s_sq [cb + nt * 8 + 1], cq1);
    }
    __syncthreads();
    if (tid < D) {
        atomicAdd(&g_sum[tid], s_sum[tid]);
        atomicAdd(&g_sq [tid], s_sq[tid]);
    }
}

// ============================================================
// finalize (parallel): BN -> fold into W2 (fp16) + bias vector
// ============================================================
__global__ __launch_bounds__(64) void finalize_kernel(
    const float* __restrict__ gamma,
    const float* __restrict__ beta,
    const float* __restrict__ W2,
    float invN)
{
    __shared__ float red[2];
    const int c = threadIdx.x;   // input channel
    const int n = blockIdx.x;    // W2 output column
    float mean = g_sum[c] * invN;
    float var  = g_sq[c] * invN - mean * mean;
    float rstd = rsqrtf(var + 1e-5f);
    float sc   = rstd * gamma[c];
    float sh   = beta[c] - mean * sc;
    float w = W2[(size_t)c * 256 + n];
    g_W2h[n * 64 + c] = __float2half_rn(sc * w);
    float b = sh * w;
#pragma unroll
    for (int off = 16; off; off >>= 1) b += __shfl_down_sync(~0u, b, off);
    if ((c & 31) == 0) red[c >> 5] = b;
    __syncthreads();
    if (c == 0) g_bias[n] = red[0] + red[1];
}

// ============================================================
// fused MLP via mma.sync fp16: 128-row tile, 4 warps,
// warp tile 32x64. GEMM1 accumulators re-packed IN REGISTERS
// as GEMM2's A fragments. out = relu(out1h @ W2' + bias) @ W3 + x
// ============================================================
__global__ __launch_bounds__(128) void mlp_mma_kernel(
    const float* __restrict__ x,
    float* __restrict__ out,
    int N)
{
    extern __shared__ __align__(16) __half sm[];
    __half* Ah  = sm;                     // 128*72
    __half* W2s = Ah + 128 * ASTRIDE;     // 64*72
    __half* W3s = W2s + 64 * ASTRIDE;     // 64*72
    __shared__ float s_bias[256];

    const int tid  = threadIdx.x;         // 0..127
    const int wid  = tid >> 5;            // 0..3
    const int lane = tid & 31;
    const int row0 = blockIdx.x * 128;

    s_bias[tid] = g_bias[tid];
    s_bias[tid + 128] = g_bias[tid + 128];

    // ---- A tile: chunk-parallel coalesced load (rows contiguous) ----
    {
        const int grp = lane >> 3;
        const int ch  = lane & 7;
#pragma unroll
        for (int i = 0; i < 8; ++i) {
            int lrow = (wid << 5) + (i << 2) + grp;
            int row = row0 + lrow;
            uint4 v = make_uint4(0, 0, 0, 0);
            if (row < N)
                v = *((const uint4*)(g_out1h + (size_t)row * D) + ch);
            *(uint4*)((char*)Ah + lrow * ASTRIDE * 2 + ch * 16) = v;
        }
    }

    const int m0 = wid * 32;

    const uint32_t uAh  = smem_u32(Ah);
    const uint32_t uW2s = smem_u32(W2s);
    const uint32_t uW3s = smem_u32(W3s);
    uint32_t oA[2];
#pragma unroll
    for (int mt = 0; mt < 2; ++mt)
        oA[mt] = (uint32_t)(((m0 + mt * 16 + (lane & 15)) * ASTRIDE + (lane >> 4) * 8) * 2);
    uint32_t oB[4];
#pragma unroll
    for (int nb = 0; nb < 4; ++nb)
        oB[nb] = (uint32_t)(((nb * 16 + (lane & 7) + ((lane >> 4) << 3)) * ASTRIDE
                             + ((lane >> 3) & 1) * 8) * 2);

    float acc2[2][8][4];
#pragma unroll
    for (int mt = 0; mt < 2; ++mt)
#pragma unroll
        for (int nt = 0; nt < 8; ++nt)
#pragma unroll
            for (int e = 0; e < 4; ++e) acc2[mt][nt][e] = 0.f;

    const int ccol = (lane & 3) * 2;

    for (int cb4 = 0; cb4 < 4; ++cb4) {
        const int c0 = cb4 * 64;

        // ---- load W2' chunk + W3 chunk (8KB each) ----
        {
            const uint4* sh2 = (const uint4*)(g_W2h + (size_t)c0 * 64);
#pragma unroll
            for (int j = 0; j < 4; ++j) {
                int f = tid + 128 * j;
                *(uint4*)((char*)(W2s + (f >> 3) * ASTRIDE) + (f & 7) * 16) = sh2[f];
                *(uint4*)((char*)(W3s + (f >> 3) * ASTRIDE) + (f & 7) * 16) =
                    *((const uint4*)(g_W3h + (size_t)(f >> 3) * 256 + c0) + (f & 7));
            }
        }
        __syncthreads();

        // ---- GEMM1 chunk: acc1 = A @ W2'c + bias ----
        float acc1[2][8][4];
#pragma unroll
        for (int mt = 0; mt < 2; ++mt)
#pragma unroll
            for (int nt = 0; nt < 8; ++nt) {
                float b0 = s_bias[c0 + nt * 8 + ccol];
                float b1 = s_bias[c0 + nt * 8 + ccol + 1];
                acc1[mt][nt][0] = b0; acc1[mt][nt][1] = b1;
                acc1[mt][nt][2] = b0; acc1[mt][nt][3] = b1;
            }

#pragma unroll
        for (int kk = 0; kk < 4; ++kk) {
            const uint32_t ko = kk * 32;
            uint32_t b[4][4];
#pragma unroll
            for (int nb = 0; nb < 4; ++nb)
                ldm_x4(b[nb], uW2s + oB[nb] + ko);
#pragma unroll
            for (int mt = 0; mt < 2; ++mt) {
                uint32_t a[4];
                ldm_x4(a, uAh + oA[mt] + ko);
#pragma unroll
                for (int nb = 0; nb < 4; ++nb) {
                    mma_f16(acc1[mt][2 * nb],     a, b[nb]);
                    mma_f16(acc1[mt][2 * nb + 1], a, b[nb] + 2);
                }
            }
        }

        // ---- relu + pack acc1 -> GEMM2 A fragments (registers only) ----
        uint32_t af[2][4][4];
#pragma unroll
        for (int mt = 0; mt < 2; ++mt)
#pragma unroll
            for (int kt = 0; kt < 4; ++kt) {
                af[mt][kt][0] = relu_h2(acc1[mt][2 * kt][0],     acc1[mt][2 * kt][1]);
                af[mt][kt][1] = relu_h2(acc1[mt][2 * kt][2],     acc1[mt][2 * kt][3]);
                af[mt][kt][2] = relu_h2(acc1[mt][2 * kt + 1][0], acc1[mt][2 * kt + 1][1]);
                af[mt][kt][3] = relu_h2(acc1[mt][2 * kt + 1][2], acc1[mt][2 * kt + 1][3]);
            }

        // ---- GEMM2 chunk: acc2 += relu(T) @ W3c, A from registers ----
#pragma unroll
        for (int kt = 0; kt < 4; ++kt) {
            const uint32_t ko = kt * 32;
            uint32_t b[4][4];
#pragma unroll
            for (int nb = 0; nb < 4; ++nb)
                ldm_x4(b[nb], uW3s + oB[nb] + ko);
#pragma unroll
            for (int mt = 0; mt < 2; ++mt) {
#pragma unroll
                for (int nb = 0; nb < 4; ++nb) {
                    mma_f16(acc2[mt][2 * nb],     af[mt][kt], b[nb]);
                    mma_f16(acc2[mt][2 * nb + 1], af[mt][kt], b[nb] + 2);
                }
            }
        }
        __syncthreads();   // all warps done with W2s/W3s before refill
    }

    // ---- epilogue: residual + store ----
#pragma unroll
    for (int mt = 0; mt < 2; ++mt) {
        int r0 = row0 + m0 + mt * 16 + (lane >> 2);
        int r1 = r0 + 8;
        if (r0 < N) {
            float* o = out + (size_t)r0 * D + ccol;
            const float* xr = x + (size_t)r0 * D + ccol;
#pragma unroll
            for (int nt = 0; nt < 8; ++nt) {
                float2 xv = *(const float2*)(xr + nt * 8);
                *(float2*)(o + nt * 8) =
                    make_float2(acc2[mt][nt][0] + xv.x, acc2[mt][nt][1] + xv.y);
            }
        }
        if (r1 < N) {
            float* o = out + (size_t)r1 * D + ccol;
            const float* xr = x + (size_t)r1 * D + ccol;
#pragma unroll
            for (int nt = 0; nt < 8; ++nt) {
                float2 xv = *(const float2*)(xr + nt * 8);
                *(float2*)(o + nt * 8) =
                    make_float2(acc2[mt][nt][2] + xv.x, acc2[mt][nt][3] + xv.y);
            }
        }
    }
}

// ============================================================
// launch
// ============================================================
extern "C" void kernel_launch(void* const* d_in, const int* in_sizes, int n_in,
                              void* d_out, int out_size)
{
    const float* x     = (const float*)d_in[0];
    const int*   nidx  = (const int*)  d_in[1];
    const int*   nmask = (const int*)  d_in[2];
    const float* W1    = (const float*)d_in[3];
    const float* gamma = (const float*)d_in[4];
    const float* beta  = (const float*)d_in[5];
    const float* W2    = (const float*)d_in[6];
    const float* W3    = (const float*)d_in[7];
    float* out = (float*)d_out;

    const int N = in_sizes[0] / D;
    const int K = in_sizes[1] / N;

    const int conv_smem = STAGE_HALVES * 2 * 2;                      // 2 stages
    cudaFuncSetAttribute(conv1_mma_kernel, cudaFuncAttributeMaxDynamicSharedMemorySize, conv_smem);
    const int mlp_smem = (128 * ASTRIDE + 64 * ASTRIDE * 2) * 2;     // A + W2 + W3
    cudaFuncSetAttribute(mlp_mma_kernel, cudaFuncAttributeMaxDynamicSharedMemorySize, mlp_smem);

    const int total8 = N * D / 8;
    prep_kernel<<<(total8 + 255) / 256, 256>>>(x, W1, W3, total8, K);
    conv1_mma_kernel<<<(N + 127) / 128, 128, conv_smem>>>(nidx, nmask, N, K);
    finalize_kernel<<<256, 64>>>(gamma, beta, W2, 1.0f / (float)N);
    mlp_mma_kernel<<<(N + 127) / 128, 128, mlp_smem>>>(x, out, N);
}

// round 15
// speedup vs baseline: 1.8065x; 1.0742x over previous
#include <cuda_runtime.h>
#include <cuda_fp16.h>
#include <cstdint>

#define D 64
#define MAXN 150208
#define KMAX 27
#define ASTRIDE 72

// ---- scratch (static device arrays: allocation-free) ----
__device__ __half g_out1h[(size_t)MAXN * D];  // conv1 output (fp16)
__device__ float g_sum[D];
__device__ float g_sq[D];
__device__ float g_bias[256];                 // sh @ W2
__device__ __half g_xh[(size_t)MAXN * D];     // x rounded to fp16
__device__ __half g_W1h[(size_t)KMAX * 4096]; // W1^T [k][n][c] fp16
__device__ __half g_W2h[256 * 64];            // (sc*W2)^T [n][c] fp16 (post-BN fold)
__device__ __half g_W3h[64 * 256];            // W3^T [n][c] fp16
__device__ int g_cidx[(size_t)KMAX * MAXN];   // mask ? idx : -1

// ============================================================
// helpers
// ============================================================
__device__ __forceinline__ uint32_t smem_u32(const void* p) {
    uint32_t a;
    asm("{ .reg .u64 t; cvta.to.shared.u64 t, %1; cvt.u32.u64 %0, t; }" : "=r"(a) : "l"(p));
    return a;
}

__device__ __forceinline__ void ldm_x4(uint32_t* r, uint32_t addr) {
    asm volatile("ldmatrix.sync.aligned.m8n8.x4.shared.b16 {%0,%1,%2,%3}, [%4];"
                 : "=r"(r[0]), "=r"(r[1]), "=r"(r[2]), "=r"(r[3]) : "r"(addr));
}

__device__ __forceinline__ void mma_f16(float* d, const uint32_t* a, const uint32_t* b) {
    asm volatile(
        "mma.sync.aligned.m16n8k16.row.col.f32.f16.f16.f32 "
        "{%0,%1,%2,%3},{%4,%5,%6,%7},{%8,%9},{%0,%1,%2,%3};"
        : "+f"(d[0]), "+f"(d[1]), "+f"(d[2]), "+f"(d[3])
        : "r"(a[0]), "r"(a[1]), "r"(a[2]), "r"(a[3]), "r"(b[0]), "r"(b[1]));
}

__device__ __forceinline__ void cpa16(uint32_t dst, const void* src, uint32_t sz) {
    asm volatile("cp.async.cg.shared.global [%0], [%1], 16, %2;"
                 :: "r"(dst), "l"(src), "r"(sz) : "memory");
}
#define CPA_COMMIT() asm volatile("cp.async.commit_group;" ::: "memory")
#define CPA_WAIT0()  asm volatile("cp.async.wait_group 0;" ::: "memory")
#define CPA_WAIT1()  asm volatile("cp.async.wait_group 1;" ::: "memory")

__device__ __forceinline__ uint32_t relu_h2(float a, float b) {
    __half2 h = __floats2half2_rn(fmaxf(a, 0.f), fmaxf(b, 0.f));
    return *(uint32_t*)&h;
}

// ============================================================
// prep (single kernel): x->fp16, W1^T, W3^T, cidx, zero stats
// ============================================================
__global__ void prep_kernel(const float* __restrict__ x,
                            const float* __restrict__ W1,
                            const float* __restrict__ W3,
                            const int* __restrict__ nbr_idx,
                            const int* __restrict__ nbr_mask,
                            int total8, int N, int K) {
    const int tid = threadIdx.x;
    if (blockIdx.x == 0) {
        if (tid < D) { g_sum[tid] = 0.f; g_sq[tid] = 0.f; }
        for (int e = tid; e < 64 * 256; e += blockDim.x) {
            int n = e >> 8, c = e & 255;
            g_W3h[n * 256 + c] = __float2half_rn(W3[(size_t)c * 64 + n]);
        }
    }
    if (blockIdx.x < (unsigned)K) {
        const float* Wk = W1 + (size_t)blockIdx.x * 4096;
        __half* dh = g_W1h + (size_t)blockIdx.x * 4096;
        for (int e = tid; e < 4096; e += blockDim.x) {
            int n = e >> 6, c = e & 63;
            dh[n * 64 + c] = __float2half_rn(Wk[c * 64 + n]);
        }
    }
    // combined index: mask ? idx : -1 (grid-stride)
    {
        const size_t total = (size_t)N * K;
        for (size_t e = (size_t)blockIdx.x * blockDim.x + tid; e < total;
             e += (size_t)gridDim.x * blockDim.x)
            g_cidx[e] = nbr_mask[e] ? nbr_idx[e] : -1;
    }
    int e = blockIdx.x * blockDim.x + tid;
    if (e >= total8) return;
    const float4* s = (const float4*)x + 2 * e;
    float4 a = s[0], b = s[1];
    uint4 o;
    __half2 h;
    h = __floats2half2_rn(a.x, a.y); o.x = *(uint32_t*)&h;
    h = __floats2half2_rn(a.z, a.w); o.y = *(uint32_t*)&h;
    h = __floats2half2_rn(b.x, b.y); o.z = *(uint32_t*)&h;
    h = __floats2half2_rn(b.z, b.w); o.w = *(uint32_t*)&h;
    ((uint4*)g_xh)[e] = o;
}

// ============================================================
// conv1 via mma.sync fp16: 128x64 tile per CTA, 4 warps,
// warp tile 32x64. Double-buffered cp.async + idx prefetch.
// 4 CTAs/SM (16 warps) for latency hiding.
// ============================================================
#define STAGE_HALVES ((128 + 64) * ASTRIDE)   // A + W, halves per stage
__global__ __launch_bounds__(128, 4) void conv1_mma_kernel(int N, int K)
{
    extern __shared__ __align__(16) __half sm[];
    __shared__ float s_sum[D], s_sq[D];

    const int tid  = threadIdx.x;         // 0..127
    const int wid  = tid >> 5;            // 0..3
    const int lane = tid & 31;
    const int row0 = blockIdx.x * 128;

    if (tid < D) { s_sum[tid] = 0.f; s_sq[tid] = 0.f; }

    const int grow = row0 + tid;          // 1 row per thread
    const bool rowok = grow < N;
    const uint32_t uBase = smem_u32(sm);
    const uint32_t stageB = STAGE_HALVES * 2;   // bytes per stage

    const uint32_t aSm = uBase + (uint32_t)(tid * ASTRIDE) * 2;
    uint32_t wSm[4];
#pragma unroll
    for (int j = 0; j < 4; ++j) {
        int f = tid + 128 * j;
        wSm[j] = uBase + (uint32_t)(128 * ASTRIDE + (f >> 3) * ASTRIDE) * 2 + (f & 7) * 16;
    }

    const int m0 = wid * 32;
    uint32_t aA[2];
#pragma unroll
    for (int mt = 0; mt < 2; ++mt)
        aA[mt] = uBase + (uint32_t)(((m0 + mt * 16 + (lane & 15)) * ASTRIDE
                                     + (lane >> 4) * 8) * 2);
    uint32_t aB[4];
#pragma unroll
    for (int nb = 0; nb < 4; ++nb)
        aB[nb] = uBase + (uint32_t)((128 * ASTRIDE
                  + (nb * 16 + (lane & 7) + ((lane >> 4) << 3)) * ASTRIDE
                  + ((lane >> 3) & 1) * 8) * 2);

    float acc[2][8][4];
#pragma unroll
    for (int mt = 0; mt < 2; ++mt)
#pragma unroll
        for (int nt = 0; nt < 8; ++nt)
#pragma unroll
            for (int e = 0; e < 4; ++e) acc[mt][nt][e] = 0.f;

    auto issue = [&](int k, int s, int idx) {
        const uint32_t so = (uint32_t)s * stageB;
        const char* wb = (const char*)(g_W1h + (size_t)k * 4096);
#pragma unroll
        for (int j = 0; j < 4; ++j)
            cpa16(wSm[j] + so, wb + (size_t)((tid + 128 * j) * 16), 16);
        int safe = idx < 0 ? 0 : idx;
        const char* src = (const char*)(g_xh + (size_t)safe * D);
        uint32_t z = idx < 0 ? 0u : 16u;
#pragma unroll
        for (int j = 0; j < 8; ++j)
            cpa16(aSm + so + j * 16, src + j * 16, z);
        CPA_COMMIT();
    };

    // prefetched index registers (single LDG per k, chained one iter ahead)
    int c_cur = rowok ? g_cidx[grow] : -1;
    issue(0, 0, c_cur);
    int c_nxt = (K > 1 && rowok) ? g_cidx[(size_t)N + grow] : -1;

    for (int k = 0; k < K; ++k) {
        const int s = k & 1;
        if (k + 1 < K) {
            issue(k + 1, s ^ 1, c_nxt);
            if (k + 2 < K)   // launch LDG now; consumed next iteration
                c_nxt = rowok ? g_cidx[(size_t)(k + 2) * N + grow] : -1;
            CPA_WAIT1();
        } else {
            CPA_WAIT0();
        }
        __syncthreads();

        const uint32_t so = (uint32_t)s * stageB;
#pragma unroll
        for (int kk = 0; kk < 4; ++kk) {
            const uint32_t ko = kk * 32;
            uint32_t b[4][4];
#pragma unroll
            for (int nb = 0; nb < 4; ++nb)
                ldm_x4(b[nb], aB[nb] + so + ko);
#pragma unroll
            for (int mt = 0; mt < 2; ++mt) {
                uint32_t a[4];
                ldm_x4(a, aA[mt] + so + ko);
#pragma unroll
                for (int nb = 0; nb < 4; ++nb) {
                    mma_f16(acc[mt][2 * nb],     a, b[nb]);
                    mma_f16(acc[mt][2 * nb + 1], a, b[nb] + 2);
                }
            }
        }
        __syncthreads();   // all warps done with stage s before refill
    }

    // ---- epilogue: fp16 store + BN-stat accumulation ----
    const int cb = (lane & 3) * 2;
#pragma unroll
    for (int mt = 0; mt < 2; ++mt) {
        int r0 = row0 + m0 + mt * 16 + (lane >> 2);
        int r1 = r0 + 8;
        if (r0 < N) {
            __half* o = g_out1h + (size_t)r0 * D + cb;
#pragma unroll
            for (int nt = 0; nt < 8; ++nt)
                *(__half2*)(o + nt * 8) = __floats2half2_rn(acc[mt][nt][0], acc[mt][nt][1]);
        }
        if (r1 < N) {
            __half* o = g_out1h + (size_t)r1 * D + cb;
#pragma unroll
            for (int nt = 0; nt < 8; ++nt)
                *(__half2*)(o + nt * 8) = __floats2half2_rn(acc[mt][nt][2], acc[mt][nt][3]);
        }
    }
    // stats: pad rows hold exact zeros -> safe unmasked
#pragma unroll
    for (int nt = 0; nt < 8; ++nt) {
        float cs0 = 0.f, cq0 = 0.f, cs1 = 0.f, cq1 = 0.f;
#pragma unroll
        for (int mt = 0; mt < 2; ++mt) {
            float a0 = acc[mt][nt][0], a2 = acc[mt][nt][2];
            float a1 = acc[mt][nt][1], a3 = acc[mt][nt][3];
            cs0 += a0 + a2; cq0 += a0 * a0 + a2 * a2;
            cs1 += a1 + a3; cq1 += a1 * a1 + a3 * a3;
        }
        atomicAdd(&s_sum[cb + nt * 8 + 0], cs0);
        atomicAdd(&s_sq [cb + nt * 8 + 0], cq0);
        atomicAdd(&s_sum[cb + nt * 8 + 1], cs1);
        atomicAdd(&s_sq [cb + nt * 8 + 1], cq1);
    }
    __syncthreads();
    if (tid < D) {
        atomicAdd(&g_sum[tid], s_sum[tid]);
        atomicAdd(&g_sq [tid], s_sq[tid]);
    }
}

// ============================================================
// finalize (parallel): BN -> fold into W2 (fp16) + bias vector
// ============================================================
__global__ __launch_bounds__(64) void finalize_kernel(
    const float* __restrict__ gamma,
    const float* __restrict__ beta,
    const float* __restrict__ W2,
    float invN)
{
    __shared__ float red[2];
    const int c = threadIdx.x;   // input channel
    const int n = blockIdx.x;    // W2 output column
    float mean = g_sum[c] * invN;
    float var  = g_sq[c] * invN - mean * mean;
    float rstd = rsqrtf(var + 1e-5f);
    float sc   = rstd * gamma[c];
    float sh   = beta[c] - mean * sc;
    float w = W2[(size_t)c * 256 + n];
    g_W2h[n * 64 + c] = __float2half_rn(sc * w);
    float b = sh * w;
#pragma unroll
    for (int off = 16; off; off >>= 1) b += __shfl_down_sync(~0u, b, off);
    if ((c & 31) == 0) red[c >> 5] = b;
    __syncthreads();
    if (c == 0) g_bias[n] = red[0] + red[1];
}

// ============================================================
// fused MLP via mma.sync fp16: 128-row tile, 4 warps,
// warp tile 32x64. GEMM1 accumulators re-packed IN REGISTERS
// as GEMM2's A fragments. out = relu(out1h @ W2' + bias) @ W3 + x
// ============================================================
__global__ __launch_bounds__(128) void mlp_mma_kernel(
    const float* __restrict__ x,
    float* __restrict__ out,
    int N)
{
    extern __shared__ __align__(16) __half sm[];
    __half* Ah  = sm;                     // 128*72
    __half* W2s = Ah + 128 * ASTRIDE;     // 64*72
    __half* W3s = W2s + 64 * ASTRIDE;     // 64*72
    __shared__ float s_bias[256];

    const int tid  = threadIdx.x;         // 0..127
    const int wid  = tid >> 5;            // 0..3
    const int lane = tid & 31;
    const int row0 = blockIdx.x * 128;

    s_bias[tid] = g_bias[tid];
    s_bias[tid + 128] = g_bias[tid + 128];

    // ---- A tile: chunk-parallel coalesced load (rows contiguous) ----
    {
        const int grp = lane >> 3;
        const int ch  = lane & 7;
#pragma unroll
        for (int i = 0; i < 8; ++i) {
            int lrow = (wid << 5) + (i << 2) + grp;
            int row = row0 + lrow;
            uint4 v = make_uint4(0, 0, 0, 0);
            if (row < N)
                v = *((const uint4*)(g_out1h + (size_t)row * D) + ch);
            *(uint4*)((char*)Ah + lrow * ASTRIDE * 2 + ch * 16) = v;
        }
    }

    const int m0 = wid * 32;

    const uint32_t uAh  = smem_u32(Ah);
    const uint32_t uW2s = smem_u32(W2s);
    const uint32_t uW3s = smem_u32(W3s);
    uint32_t oA[2];
#pragma unroll
    for (int mt = 0; mt < 2; ++mt)
        oA[mt] = (uint32_t)(((m0 + mt * 16 + (lane & 15)) * ASTRIDE + (lane >> 4) * 8) * 2);
    uint32_t oB[4];
#pragma unroll
    for (int nb = 0; nb < 4; ++nb)
        oB[nb] = (uint32_t)(((nb * 16 + (lane & 7) + ((lane >> 4) << 3)) * ASTRIDE
                             + ((lane >> 3) & 1) * 8) * 2);

    float acc2[2][8][4];
#pragma unroll
    for (int mt = 0; mt < 2; ++mt)
#pragma unroll
        for (int nt = 0; nt < 8; ++nt)
#pragma unroll
            for (int e = 0; e < 4; ++e) acc2[mt][nt][e] = 0.f;

    const int ccol = (lane & 3) * 2;

    for (int cb4 = 0; cb4 < 4; ++cb4) {
        const int c0 = cb4 * 64;

        // ---- load W2' chunk + W3 chunk (8KB each) ----
        {
            const uint4* sh2 = (const uint4*)(g_W2h + (size_t)c0 * 64);
#pragma unroll
            for (int j = 0; j < 4; ++j) {
                int f = tid + 128 * j;
                *(uint4*)((char*)(W2s + (f >> 3) * ASTRIDE) + (f & 7) * 16) = sh2[f];
                *(uint4*)((char*)(W3s + (f >> 3) * ASTRIDE) + (f & 7) * 16) =
                    *((const uint4*)(g_W3h + (size_t)(f >> 3) * 256 + c0) + (f & 7));
            }
        }
        __syncthreads();

        // ---- GEMM1 chunk: acc1 = A @ W2'c + bias ----
        float acc1[2][8][4];
#pragma unroll
        for (int mt = 0; mt < 2; ++mt)
#pragma unroll
            for (int nt = 0; nt < 8; ++nt) {
                float b0 = s_bias[c0 + nt * 8 + ccol];
                float b1 = s_bias[c0 + nt * 8 + ccol + 1];
                acc1[mt][nt][0] = b0; acc1[mt][nt][1] = b1;
                acc1[mt][nt][2] = b0; acc1[mt][nt][3] = b1;
            }

#pragma unroll
        for (int kk = 0; kk < 4; ++kk) {
            const uint32_t ko = kk * 32;
            uint32_t b[4][4];
#pragma unroll
            for (int nb = 0; nb < 4; ++nb)
                ldm_x4(b[nb], uW2s + oB[nb] + ko);
#pragma unroll
            for (int mt = 0; mt < 2; ++mt) {
                uint32_t a[4];
                ldm_x4(a, uAh + oA[mt] + ko);
#pragma unroll
                for (int nb = 0; nb < 4; ++nb) {
                    mma_f16(acc1[mt][2 * nb],     a, b[nb]);
                    mma_f16(acc1[mt][2 * nb + 1], a, b[nb] + 2);
                }
            }
        }

        // ---- relu + pack acc1 -> GEMM2 A fragments (registers only) ----
        uint32_t af[2][4][4];
#pragma unroll
        for (int mt = 0; mt < 2; ++mt)
#pragma unroll
            for (int kt = 0; kt < 4; ++kt) {
                af[mt][kt][0] = relu_h2(acc1[mt][2 * kt][0],     acc1[mt][2 * kt][1]);
                af[mt][kt][1] = relu_h2(acc1[mt][2 * kt][2],     acc1[mt][2 * kt][3]);
                af[mt][kt][2] = relu_h2(acc1[mt][2 * kt + 1][0], acc1[mt][2 * kt + 1][1]);
                af[mt][kt][3] = relu_h2(acc1[mt][2 * kt + 1][2], acc1[mt][2 * kt + 1][3]);
            }

        // ---- GEMM2 chunk: acc2 += relu(T) @ W3c, A from registers ----
#pragma unroll
        for (int kt = 0; kt < 4; ++kt) {
            const uint32_t ko = kt * 32;
            uint32_t b[4][4];
#pragma unroll
            for (int nb = 0; nb < 4; ++nb)
                ldm_x4(b[nb], uW3s + oB[nb] + ko);
#pragma unroll
            for (int mt = 0; mt < 2; ++mt) {
#pragma unroll
                for (int nb = 0; nb < 4; ++nb) {
                    mma_f16(acc2[mt][2 * nb],     af[mt][kt], b[nb]);
                    mma_f16(acc2[mt][2 * nb + 1], af[mt][kt], b[nb] + 2);
                }
            }
        }
        __syncthreads();   // all warps done with W2s/W3s before refill
    }

    // ---- epilogue: residual + store ----
#pragma unroll
    for (int mt = 0; mt < 2; ++mt) {
        int r0 = row0 + m0 + mt * 16 + (lane >> 2);
        int r1 = r0 + 8;
        if (r0 < N) {
            float* o = out + (size_t)r0 * D + ccol;
            const float* xr = x + (size_t)r0 * D + ccol;
#pragma unroll
            for (int nt = 0; nt < 8; ++nt) {
                float2 xv = *(const float2*)(xr + nt * 8);
                *(float2*)(o + nt * 8) =
                    make_float2(acc2[mt][nt][0] + xv.x, acc2[mt][nt][1] + xv.y);
            }
        }
        if (r1 < N) {
            float* o = out + (size_t)r1 * D + ccol;
            const float* xr = x + (size_t)r1 * D + ccol;
#pragma unroll
            for (int nt = 0; nt < 8; ++nt) {
                float2 xv = *(const float2*)(xr + nt * 8);
                *(float2*)(o + nt * 8) =
                    make_float2(acc2[mt][nt][2] + xv.x, acc2[mt][nt][3] + xv.y);
            }
        }
    }
}

// ============================================================
// launch
// ============================================================
extern "C" void kernel_launch(void* const* d_in, const int* in_sizes, int n_in,
                              void* d_out, int out_size)
{
    const float* x     = (const float*)d_in[0];
    const int*   nidx  = (const int*)  d_in[1];
    const int*   nmask = (const int*)  d_in[2];
    const float* W1    = (const float*)d_in[3];
    const float* gamma = (const float*)d_in[4];
    const float* beta  = (const float*)d_in[5];
    const float* W2    = (const float*)d_in[6];
    const float* W3    = (const float*)d_in[7];
    float* out = (float*)d_out;

    const int N = in_sizes[0] / D;
    const int K = in_sizes[1] / N;

    const int conv_smem = STAGE_HALVES * 2 * 2;                      // 2 stages
    cudaFuncSetAttribute(conv1_mma_kernel, cudaFuncAttributeMaxDynamicSharedMemorySize, conv_smem);
    const int mlp_smem = (128 * ASTRIDE + 64 * ASTRIDE * 2) * 2;     // A + W2 + W3
    cudaFuncSetAttribute(mlp_mma_kernel, cudaFuncAttributeMaxDynamicSharedMemorySize, mlp_smem);

    const int total8 = N * D / 8;
    prep_kernel<<<(total8 + 255) / 256, 256>>>(x, W1, W3, nidx, nmask, total8, N, K);
    conv1_mma_kernel<<<(N + 127) / 128, 128, conv_smem>>>(N, K);
    finalize_kernel<<<256, 64>>>(gamma, beta, W2, 1.0f / (float)N);
    mlp_mma_kernel<<<(N + 127) / 128, 128, mlp_smem>>>(x, out, N);
}